// round 13
// baseline (speedup 1.0000x reference)
#include <cuda_runtime.h>
#include <cuda_bf16.h>
#include <cuda_fp16.h>
#include <math.h>
#include <stdint.h>

// Problem constants (fixed for this problem instance)
#define B_   2
#define S_   2048
#define H_   2048
#define NH_  16
#define NKV_ 4
#define HD_  128
#define T_   (B_ * S_)            // 4096 tokens
#define SCALE_ 0.08838834764831845f   // 128^-0.5

// ---------------------------------------------------------------------------
// Device scratch (allocation-free rule: __device__ globals)
// ---------------------------------------------------------------------------
__device__ float g_Q[T_ * NH_ * HD_];      // [4096, 2048]
__device__ float g_K[T_ * NKV_ * HD_];     // [4096, 512]
__device__ float g_V[T_ * NKV_ * HD_];     // [4096, 512]
__device__ float g_ATTN[T_ * NH_ * HD_];   // [4096, 2048]

// ---------------------------------------------------------------------------
// Numeric helpers
// ---------------------------------------------------------------------------
__device__ __forceinline__ void mma_f16(float* d, const uint32_t* a, const uint32_t* b) {
    asm volatile(
        "mma.sync.aligned.m16n8k16.row.col.f32.f16.f16.f32 "
        "{%0,%1,%2,%3}, {%4,%5,%6,%7}, {%8,%9}, {%0,%1,%2,%3};"
        : "+f"(d[0]), "+f"(d[1]), "+f"(d[2]), "+f"(d[3])
        : "r"(a[0]), "r"(a[1]), "r"(a[2]), "r"(a[3]), "r"(b[0]), "r"(b[1]));
}
__device__ __forceinline__ void split_f16(float x, float& h, float& l) {
    __half hb = __float2half_rn(x);
    h = __half2float(hb);
    l = x - h;
}
__device__ __forceinline__ uint32_t h2pack(float x, float y) {
    __half2 t = __floats2half2_rn(x, y);              // x -> low half (even k)
    return *reinterpret_cast<uint32_t*>(&t);
}

// ---------------------------------------------------------------------------
// Split-FP16 tensor-core GEMM, k-chunk 32, ping-pong SMEM (1 sync/chunk).
// TWO=true : C = Ah*Bh + Al*Bh ; TWO=false: C = Ah*Bh.
// Tile 128x128; 256 threads (8 warps 2x4, warp tile 64x32).
// Row stride 20 words: fragment reads (20g+tg) mod 32 are conflict-free.
// ---------------------------------------------------------------------------
#define GSTR 20
#define GTILE (128 * GSTR)          // words per tile

template<bool TWO>
__global__ __launch_bounds__(256) void f16_gemm_kernel(
    const float* __restrict__ A, const float* __restrict__ Bm,
    const float* __restrict__ bias, float* __restrict__ C,
    int M, int N, int K)
{
    extern __shared__ uint32_t gsm[];
    const int ntile = TWO ? 3 : 2;          // Ah, (Al), Bh per buffer

    const int tid  = threadIdx.x;
    const int warp = tid >> 5;
    const int lane = tid & 31;
    const int g    = lane >> 2;
    const int tg   = lane & 3;
    const int wm   = warp >> 2;
    const int wn   = warp & 3;

    const int bm = blockIdx.y;
    const int bn = blockIdx.x;

    const float* Ab = A + (size_t)(bm * 128) * K;
    const float* Bb = Bm + bn * 128;

    float acc[4][4][4];
#pragma unroll
    for (int mi = 0; mi < 4; ++mi)
#pragma unroll
        for (int ni = 0; ni < 4; ++ni)
#pragma unroll
            for (int r = 0; r < 4; ++r) acc[mi][ni][r] = 0.f;

    // load chunk (32 k) straight into smem buffer (convert inline)
    auto load_chunk = [&](int k0, int bufi) {
        uint32_t* Ahp = gsm + bufi * ntile * GTILE;
        uint32_t* Alp = Ahp + GTILE;                    // valid only if TWO
        uint32_t* Bhp = Ahp + (TWO ? 2 : 1) * GTILE;
#pragma unroll
        for (int i = 0; i < 8; ++i) {
            int p  = i * 256 + tid;
            int ar = p >> 4, ak = p & 15;               // A: 128 rows x 16 pairs
            float2 av = *(const float2*)(Ab + (size_t)ar * K + k0 + 2 * ak);
            if (TWO) {
                float hx, lx, hy, ly;
                split_f16(av.x, hx, lx);
                split_f16(av.y, hy, ly);
                Ahp[ar * GSTR + ak] = h2pack(hx, hy);
                Alp[ar * GSTR + ak] = h2pack(lx, ly);
            } else {
                Ahp[ar * GSTR + ak] = h2pack(av.x, av.y);
            }
            int bnn = p & 127, bk = (p >> 7) & 15;      // B: 128 cols x 16 pairs
            float b0 = Bb[(size_t)(k0 + 2 * bk)     * N + bnn];
            float b1 = Bb[(size_t)(k0 + 2 * bk + 1) * N + bnn];
            Bhp[bnn * GSTR + bk] = h2pack(b0, b1);
        }
    };

    auto compute_chunk = [&](int bufi) {
        uint32_t* Ahp = gsm + bufi * ntile * GTILE;
        uint32_t* Alp = Ahp + GTILE;
        uint32_t* Bhp = Ahp + (TWO ? 2 : 1) * GTILE;
#pragma unroll
        for (int ks = 0; ks < 2; ++ks) {
            const int kc = ks * 8 + tg;
            uint32_t ah[4][4], al[4][4];
            uint32_t bh[4][2];
#pragma unroll
            for (int mi = 0; mi < 4; ++mi) {
                int r0 = (wm * 64 + mi * 16 + g) * GSTR;
                ah[mi][0] = Ahp[r0 + kc];
                ah[mi][1] = Ahp[r0 + 8 * GSTR + kc];
                ah[mi][2] = Ahp[r0 + kc + 4];
                ah[mi][3] = Ahp[r0 + 8 * GSTR + kc + 4];
                if (TWO) {
                    al[mi][0] = Alp[r0 + kc];
                    al[mi][1] = Alp[r0 + 8 * GSTR + kc];
                    al[mi][2] = Alp[r0 + kc + 4];
                    al[mi][3] = Alp[r0 + 8 * GSTR + kc + 4];
                }
            }
#pragma unroll
            for (int ni = 0; ni < 4; ++ni) {
                int n0 = (wn * 32 + ni * 8 + g) * GSTR;
                bh[ni][0] = Bhp[n0 + kc];
                bh[ni][1] = Bhp[n0 + kc + 4];
            }
#pragma unroll
            for (int mi = 0; mi < 4; ++mi)
#pragma unroll
                for (int ni = 0; ni < 4; ++ni) {
                    mma_f16(acc[mi][ni], ah[mi], bh[ni]);
                    if (TWO) mma_f16(acc[mi][ni], al[mi], bh[ni]);
                }
        }
    };

    const int nch = K / 32;
    load_chunk(0, 0);
    __syncthreads();
    for (int c = 0; c < nch; ++c) {
        if (c + 1 < nch) load_chunk((c + 1) * 32, (c + 1) & 1);
        compute_chunk(c & 1);
        __syncthreads();
    }

#pragma unroll
    for (int mi = 0; mi < 4; ++mi) {
        int r0 = bm * 128 + wm * 64 + mi * 16 + g;
#pragma unroll
        for (int ni = 0; ni < 4; ++ni) {
            int c = bn * 128 + wn * 32 + ni * 8 + 2 * tg;
            float b0 = 0.f, b1 = 0.f;
            if (bias) { b0 = bias[c]; b1 = bias[c + 1]; }
            float2 o0, o1;
            o0.x = acc[mi][ni][0] + b0; o0.y = acc[mi][ni][1] + b1;
            o1.x = acc[mi][ni][2] + b0; o1.y = acc[mi][ni][3] + b1;
            *(float2*)(C + (size_t)r0 * N + c)       = o0;
            *(float2*)(C + (size_t)(r0 + 8) * N + c) = o1;
        }
    }
}

// ---------------------------------------------------------------------------
// Neox RoPE applied in-place to x[T, nheads*128].
// ---------------------------------------------------------------------------
__global__ void rope_kernel(float* __restrict__ x, const int* __restrict__ positions,
                            int Ttot, int nheads)
{
    int idx = blockIdx.x * blockDim.x + threadIdx.x;
    int total = Ttot * nheads * (HD_ / 2);
    if (idx >= total) return;
    int i = idx & 63;
    int h = (idx >> 6) % nheads;
    int t = idx / (64 * nheads);

    int pos = positions[t % S_];
    float inv_freq = powf(10000.0f, -((float)(2 * i)) / (float)HD_);
    float freq = (float)pos * inv_freq;
    float s, c;
    sincosf(freq, &s, &c);

    size_t base = (size_t)t * (nheads * HD_) + h * HD_;
    float x1 = x[base + i];
    float x2 = x[base + 64 + i];
    x[base + i]      = x1 * c - x2 * s;
    x[base + 64 + i] = x2 * c + x1 * s;
}

// ---------------------------------------------------------------------------
// FP16 tensor-core flash attention (m16n8k16, causal, GQA rep=4).
// Block: 256 threads (8 warps); BM=128 query rows, BN=128 kv cols.
// SMEM words: sQ[128][68], sK[128][68], sVt[128 dims][68] (transposed V).
// ---------------------------------------------------------------------------
#define QKW 68     // words per row (64 data + 4 pad); banks 4g+tg conflict-free
#define FA_BM2 128
#define FA_BN2 128

__global__ __launch_bounds__(256) void flash_attn_fp16_kernel(
    const float* __restrict__ Q, const float* __restrict__ K,
    const float* __restrict__ V, float* __restrict__ O)
{
    extern __shared__ uint32_t smu[];
    uint32_t* sQ  = smu;                        // 128*68
    uint32_t* sK  = sQ + FA_BM2 * QKW;          // 128*68
    uint32_t* sVt = sK + FA_BN2 * QKW;          // 128*68
    __half*   sVh = (__half*)sVt;               // halves, row stride 136

    const int qt = blockIdx.x;
    const int h  = blockIdx.y;
    const int b  = blockIdx.z;
    const int kvh = h >> 2;

    const int tid  = threadIdx.x;
    const int warp = tid >> 5;
    const int lane = tid & 31;
    const int g    = lane >> 2;   // 0..7
    const int tg   = lane & 3;    // 0..3
    const int q0   = qt * FA_BM2;
    const int w16  = warp * 16;

    const float* Qbase = Q + (size_t)b * S_ * (NH_ * HD_)  + h * HD_;
    const float* Kbase = K + (size_t)b * S_ * (NKV_ * HD_) + kvh * HD_;
    const float* Vbase = V + (size_t)b * S_ * (NKV_ * HD_) + kvh * HD_;

    // Load + fp16-convert Q tile (128 rows x 128 dims)
#pragma unroll 4
    for (int i = 0; i < 16; ++i) {
        int lin = i * 256 + tid;
        int r   = lin >> 5;
        int d4  = (lin & 31) * 4;
        float4 v = *(const float4*)(Qbase + (size_t)(q0 + r) * (NH_ * HD_) + d4);
        sQ[r * QKW + (d4 >> 1)]     = h2pack(v.x, v.y);
        sQ[r * QKW + (d4 >> 1) + 1] = h2pack(v.z, v.w);
    }

    float oacc[16][4];
#pragma unroll
    for (int n = 0; n < 16; ++n)
#pragma unroll
        for (int r = 0; r < 4; ++r) oacc[n][r] = 0.f;
    float m_i[2] = { -1e30f, -1e30f };
    float l_i[2] = { 0.f, 0.f };

    __syncthreads();

    const int njt = qt + 1;   // kv tiles of 128 covering [0, q0+128)

    for (int j = 0; j < njt; ++j) {
        const int k0 = j * FA_BN2;

        // K tile: 128 rows x 128 dims, half2 along dims
#pragma unroll 4
        for (int i = 0; i < 16; ++i) {
            int lin = i * 256 + tid;
            int r   = lin >> 5;
            int d4  = (lin & 31) * 4;
            float4 kv = *(const float4*)(Kbase + (size_t)(k0 + r) * (NKV_ * HD_) + d4);
            sK[r * QKW + (d4 >> 1)]     = h2pack(kv.x, kv.y);
            sK[r * QKW + (d4 >> 1) + 1] = h2pack(kv.z, kv.w);
        }
        // V tile transposed: scalar loads (coalesced), half stores
#pragma unroll 4
        for (int i = 0; i < 64; ++i) {
            int lin = i * 256 + tid;
            int dim = lin & 127;
            int r   = lin >> 7;
            float v = Vbase[(size_t)(k0 + r) * (NKV_ * HD_) + dim];
            sVh[dim * (2 * QKW) + r] = __float2half_rn(v);
        }
        __syncthreads();

        // Per-warp skip of fully-masked tiles (warp-uniform)
        if (k0 <= q0 + w16 + 15) {
            // ---- S = Q @ K^T (fp16 k16; warp computes 16x128) ----
            float sacc[16][4];
#pragma unroll
            for (int n = 0; n < 16; ++n)
#pragma unroll
                for (int r = 0; r < 4; ++r) sacc[n][r] = 0.f;

#pragma unroll 2
            for (int ks = 0; ks < 8; ++ks) {
                uint32_t a[4];
                const int kc = ks * 8 + tg;
                a[0] = sQ[(w16 + g)     * QKW + kc];
                a[1] = sQ[(w16 + g + 8) * QKW + kc];
                a[2] = sQ[(w16 + g)     * QKW + kc + 4];
                a[3] = sQ[(w16 + g + 8) * QKW + kc + 4];
#pragma unroll 8
                for (int n = 0; n < 16; ++n) {
                    uint32_t bfr[2];
                    bfr[0] = sK[(n * 8 + g) * QKW + kc];
                    bfr[1] = sK[(n * 8 + g) * QKW + kc + 4];
                    mma_f16(sacc[n], a, bfr);
                }
            }

            // ---- scale + causal mask ----
            const int r0g = q0 + w16 + g;
            const int r1g = r0g + 8;
            const bool diag = (k0 + FA_BN2 - 1 > q0 + w16);
#pragma unroll
            for (int n = 0; n < 16; ++n) {
                int cb = k0 + n * 8 + 2 * tg;
                float s0 = sacc[n][0] * SCALE_;
                float s1 = sacc[n][1] * SCALE_;
                float s2 = sacc[n][2] * SCALE_;
                float s3 = sacc[n][3] * SCALE_;
                if (diag) {
                    if (cb     > r0g) s0 = -1e30f;
                    if (cb + 1 > r0g) s1 = -1e30f;
                    if (cb     > r1g) s2 = -1e30f;
                    if (cb + 1 > r1g) s3 = -1e30f;
                }
                sacc[n][0] = s0; sacc[n][1] = s1; sacc[n][2] = s2; sacc[n][3] = s3;
            }

            // ---- online softmax ----
            float mx0 = -1e30f, mx1 = -1e30f;
#pragma unroll
            for (int n = 0; n < 16; ++n) {
                mx0 = fmaxf(mx0, fmaxf(sacc[n][0], sacc[n][1]));
                mx1 = fmaxf(mx1, fmaxf(sacc[n][2], sacc[n][3]));
            }
            mx0 = fmaxf(mx0, __shfl_xor_sync(0xffffffffu, mx0, 1));
            mx0 = fmaxf(mx0, __shfl_xor_sync(0xffffffffu, mx0, 2));
            mx1 = fmaxf(mx1, __shfl_xor_sync(0xffffffffu, mx1, 1));
            mx1 = fmaxf(mx1, __shfl_xor_sync(0xffffffffu, mx1, 2));

            float mn0 = fmaxf(m_i[0], mx0);
            float mn1 = fmaxf(m_i[1], mx1);
            float al0 = __expf(m_i[0] - mn0);
            float al1 = __expf(m_i[1] - mn1);
            m_i[0] = mn0; m_i[1] = mn1;

            // exp + pack P into fp16 A-fragment words (no shuffles at k16)
            uint32_t pk[16][2];
            float rs0 = 0.f, rs1 = 0.f;
#pragma unroll
            for (int n = 0; n < 16; ++n) {
                float p0 = __expf(sacc[n][0] - mn0);
                float p1 = __expf(sacc[n][1] - mn0);
                float p2 = __expf(sacc[n][2] - mn1);
                float p3 = __expf(sacc[n][3] - mn1);
                rs0 += p0 + p1;
                rs1 += p2 + p3;
                pk[n][0] = h2pack(p0, p1);
                pk[n][1] = h2pack(p2, p3);
            }
            rs0 += __shfl_xor_sync(0xffffffffu, rs0, 1);
            rs0 += __shfl_xor_sync(0xffffffffu, rs0, 2);
            rs1 += __shfl_xor_sync(0xffffffffu, rs1, 1);
            rs1 += __shfl_xor_sync(0xffffffffu, rs1, 2);
            l_i[0] = l_i[0] * al0 + rs0;
            l_i[1] = l_i[1] * al1 + rs1;

            // rescale O accumulator
#pragma unroll
            for (int n = 0; n < 16; ++n) {
                oacc[n][0] *= al0; oacc[n][1] *= al0;
                oacc[n][2] *= al1; oacc[n][3] *= al1;
            }

            // ---- O += P @ V (fp16 k16, V transposed in smem) ----
#pragma unroll 2
            for (int ks = 0; ks < 8; ++ks) {
                uint32_t a[4];
                a[0] = pk[2 * ks][0];
                a[1] = pk[2 * ks][1];
                a[2] = pk[2 * ks + 1][0];
                a[3] = pk[2 * ks + 1][1];
                const int kc = ks * 8 + tg;
#pragma unroll 8
                for (int n = 0; n < 16; ++n) {
                    uint32_t bfr[2];
                    bfr[0] = sVt[(n * 8 + g) * QKW + kc];
                    bfr[1] = sVt[(n * 8 + g) * QKW + kc + 4];
                    mma_f16(oacc[n], a, bfr);
                }
            }
        }
        __syncthreads();   // protect sK/sVt before next iteration
    }

    // ---- epilogue: divide by l, write out ----
    float inv0 = 1.0f / l_i[0];
    float inv1 = 1.0f / l_i[1];
    size_t t0 = (size_t)b * S_ + q0 + w16 + g;
    size_t t1 = t0 + 8;
    float* op0 = O + t0 * (NH_ * HD_) + h * HD_;
    float* op1 = O + t1 * (NH_ * HD_) + h * HD_;
#pragma unroll
    for (int n = 0; n < 16; ++n) {
        int c = n * 8 + 2 * tg;
        float2 v0, v1;
        v0.x = oacc[n][0] * inv0; v0.y = oacc[n][1] * inv0;
        v1.x = oacc[n][2] * inv1; v1.y = oacc[n][3] * inv1;
        *(float2*)(op0 + c) = v0;
        *(float2*)(op1 + c) = v1;
    }
}

// ---------------------------------------------------------------------------
// Launch
// ---------------------------------------------------------------------------
extern "C" void kernel_launch(void* const* d_in, const int* in_sizes, int n_in,
                              void* d_out, int out_size)
{
    const float* hidden = (const float*)d_in[0];
    const int*   positions = (const int*)d_in[1];
    const float* Wq = (const float*)d_in[2];
    const float* bq = (const float*)d_in[3];
    const float* Wk = (const float*)d_in[4];
    const float* bk = (const float*)d_in[5];
    const float* Wv = (const float*)d_in[6];
    const float* bv = (const float*)d_in[7];
    const float* Wo = (const float*)d_in[8];
    float* out = (float*)d_out;

    void *pQ, *pK, *pV, *pA;
    cudaGetSymbolAddress(&pQ, g_Q);
    cudaGetSymbolAddress(&pK, g_K);
    cudaGetSymbolAddress(&pV, g_V);
    cudaGetSymbolAddress(&pA, g_ATTN);
    float* Qs = (float*)pQ;
    float* Ks = (float*)pK;
    float* Vs = (float*)pV;
    float* As = (float*)pA;

    const int smem2 = 2 * 3 * GTILE * 4;   // TWO buffers: Ah+Al+Bh  (61440 B)
    const int smem1 = 2 * 2 * GTILE * 4;   // one-term:    Ah+Bh     (40960 B)
    cudaFuncSetAttribute(f16_gemm_kernel<true>,  cudaFuncAttributeMaxDynamicSharedMemorySize, smem2);
    cudaFuncSetAttribute(f16_gemm_kernel<false>, cudaFuncAttributeMaxDynamicSharedMemorySize, smem1);

    // QKV projections (split-fp16, 2-term)
    f16_gemm_kernel<true><<<dim3((NH_ * HD_) / 128, T_ / 128), 256, smem2>>>(hidden, Wq, bq, Qs, T_, NH_ * HD_, H_);
    f16_gemm_kernel<true><<<dim3((NKV_ * HD_) / 128, T_ / 128), 256, smem2>>>(hidden, Wk, bk, Ks, T_, NKV_ * HD_, H_);
    f16_gemm_kernel<true><<<dim3((NKV_ * HD_) / 128, T_ / 128), 256, smem2>>>(hidden, Wv, bv, Vs, T_, NKV_ * HD_, H_);

    // RoPE on Q and K
    {
        int totq = T_ * NH_ * 64;
        rope_kernel<<<(totq + 255) / 256, 256>>>(Qs, positions, T_, NH_);
        int totk = T_ * NKV_ * 64;
        rope_kernel<<<(totk + 255) / 256, 256>>>(Ks, positions, T_, NKV_);
    }

    // FP16 tensor-core flash attention (BM=128, BN=128, 8 warps)
    size_t fa_smem = (size_t)(FA_BM2 * QKW + FA_BN2 * QKW + FA_BN2 * QKW) * sizeof(uint32_t);
    cudaFuncSetAttribute(flash_attn_fp16_kernel, cudaFuncAttributeMaxDynamicSharedMemorySize, (int)fa_smem);
    flash_attn_fp16_kernel<<<dim3(S_ / FA_BM2, NH_, B_), 256, fa_smem>>>(Qs, Ks, Vs, As);

    // Output projection (plain fp16, 1-term)
    f16_gemm_kernel<false><<<dim3(H_ / 128, T_ / 128), 256, smem1>>>(As, Wo, nullptr, out, T_, H_, NH_ * HD_);
}

// round 14
// speedup vs baseline: 1.5358x; 1.5358x over previous
#include <cuda_runtime.h>
#include <cuda_bf16.h>
#include <cuda_fp16.h>
#include <math.h>
#include <stdint.h>

// Problem constants (fixed for this problem instance)
#define B_   2
#define S_   2048
#define H_   2048
#define NH_  16
#define NKV_ 4
#define HD_  128
#define T_   (B_ * S_)            // 4096 tokens
#define SCALE_ 0.08838834764831845f   // 128^-0.5

// ---------------------------------------------------------------------------
// Device scratch (allocation-free rule: __device__ globals)
// ---------------------------------------------------------------------------
__device__ float g_Q[T_ * NH_ * HD_];      // [4096, 2048]
__device__ float g_K[T_ * NKV_ * HD_];     // [4096, 512]
__device__ float g_V[T_ * NKV_ * HD_];     // [4096, 512]
__device__ float g_ATTN[T_ * NH_ * HD_];   // [4096, 2048]

// ---------------------------------------------------------------------------
// Numeric helpers
// ---------------------------------------------------------------------------
__device__ __forceinline__ void mma_f16(float* d, const uint32_t* a, const uint32_t* b) {
    asm volatile(
        "mma.sync.aligned.m16n8k16.row.col.f32.f16.f16.f32 "
        "{%0,%1,%2,%3}, {%4,%5,%6,%7}, {%8,%9}, {%0,%1,%2,%3};"
        : "+f"(d[0]), "+f"(d[1]), "+f"(d[2]), "+f"(d[3])
        : "r"(a[0]), "r"(a[1]), "r"(a[2]), "r"(a[3]), "r"(b[0]), "r"(b[1]));
}
__device__ __forceinline__ void split_f16(float x, float& h, float& l) {
    __half hb = __float2half_rn(x);
    h = __half2float(hb);
    l = x - h;
}
__device__ __forceinline__ uint32_t h2pack(float x, float y) {
    __half2 t = __floats2half2_rn(x, y);              // x -> low half (even k)
    return *reinterpret_cast<uint32_t*>(&t);
}

// ---------------------------------------------------------------------------
// Split-FP16 tensor-core GEMM, double-buffered SMEM, ONE sync per k16 tile.
// TWO=true : C = Ah*Bh + Al*Bh ; TWO=false: C = Ah*Bh.
// Tile 128x128x16; 256 threads (8 warps 2x4, warp tile 64x32).
// SMEM rows padded to 12 words (12g+tg mod 32 conflict-free). Static 2x buffers.
// ---------------------------------------------------------------------------
#define GB_STRIDE 12
#define GB_TILE   (128 * GB_STRIDE)

template<bool TWO>
__global__ __launch_bounds__(256) void f16_gemm_kernel(
    const float* __restrict__ A, const float* __restrict__ Bm,
    const float* __restrict__ bias, float* __restrict__ C,
    int M, int N, int K)
{
    __shared__ uint32_t Ah[2][GB_TILE];
    __shared__ uint32_t Al[TWO ? 2 : 1][TWO ? GB_TILE : 32];
    __shared__ uint32_t Bh[2][GB_TILE];

    const int tid  = threadIdx.x;
    const int warp = tid >> 5;
    const int lane = tid & 31;
    const int g    = lane >> 2;
    const int tg   = lane & 3;
    const int wm   = warp >> 2;
    const int wn   = warp & 3;

    const int bm = blockIdx.y;
    const int bn = blockIdx.x;

    const float* Ab = A + (size_t)(bm * 128) * K;
    const float* Bb = Bm + bn * 128;

    float acc[4][4][4];
#pragma unroll
    for (int mi = 0; mi < 4; ++mi)
#pragma unroll
        for (int ni = 0; ni < 4; ++ni)
#pragma unroll
            for (int r = 0; r < 4; ++r) acc[mi][ni][r] = 0.f;

    float2 aReg[4];
    float  bReg[4][2];

    auto load_tile = [&](int k0) {
#pragma unroll
        for (int i = 0; i < 4; ++i) {
            int p  = i * 256 + tid;
            int ar = p >> 3, ak = p & 7;
            aReg[i] = *(const float2*)(Ab + (size_t)ar * K + k0 + 2 * ak);
            int bk = (p >> 7) & 7, bnn = p & 127;
            bReg[i][0] = Bb[(size_t)(k0 + 2 * bk)     * N + bnn];
            bReg[i][1] = Bb[(size_t)(k0 + 2 * bk + 1) * N + bnn];
        }
    };
    auto store_tile = [&](int buf) {
#pragma unroll
        for (int i = 0; i < 4; ++i) {
            int p  = i * 256 + tid;
            int ar = p >> 3, ak = p & 7;
            if (TWO) {
                float hx, lx, hy, ly;
                split_f16(aReg[i].x, hx, lx);
                split_f16(aReg[i].y, hy, ly);
                Ah[buf][ar * GB_STRIDE + ak] = h2pack(hx, hy);
                Al[buf][ar * GB_STRIDE + ak] = h2pack(lx, ly);
            } else {
                Ah[buf][ar * GB_STRIDE + ak] = h2pack(aReg[i].x, aReg[i].y);
            }
            int bk = (p >> 7) & 7, bnn = p & 127;
            Bh[buf][bnn * GB_STRIDE + bk] = h2pack(bReg[i][0], bReg[i][1]);
        }
    };
    auto compute_tile = [&](int buf) {
        uint32_t ah[4][4], al[4][4];
        uint32_t bh[4][2];
#pragma unroll
        for (int mi = 0; mi < 4; ++mi) {
            int r0 = (wm * 64 + mi * 16 + g) * GB_STRIDE;
            ah[mi][0] = Ah[buf][r0 + tg];
            ah[mi][1] = Ah[buf][r0 + 8 * GB_STRIDE + tg];
            ah[mi][2] = Ah[buf][r0 + tg + 4];
            ah[mi][3] = Ah[buf][r0 + 8 * GB_STRIDE + tg + 4];
            if (TWO) {
                al[mi][0] = Al[buf][r0 + tg];
                al[mi][1] = Al[buf][r0 + 8 * GB_STRIDE + tg];
                al[mi][2] = Al[buf][r0 + tg + 4];
                al[mi][3] = Al[buf][r0 + 8 * GB_STRIDE + tg + 4];
            }
        }
#pragma unroll
        for (int ni = 0; ni < 4; ++ni) {
            int n0 = (wn * 32 + ni * 8 + g) * GB_STRIDE;
            bh[ni][0] = Bh[buf][n0 + tg];
            bh[ni][1] = Bh[buf][n0 + tg + 4];
        }
#pragma unroll
        for (int mi = 0; mi < 4; ++mi)
#pragma unroll
            for (int ni = 0; ni < 4; ++ni) {
                mma_f16(acc[mi][ni], ah[mi], bh[ni]);
                if (TWO) mma_f16(acc[mi][ni], al[mi], bh[ni]);
            }
    };

    const int ntiles = K / 16;

    load_tile(0);
    store_tile(0);
    __syncthreads();

    for (int t = 0; t < ntiles; ++t) {
        if (t + 1 < ntiles) load_tile((t + 1) * 16);   // global loads issue early
        compute_tile(t & 1);                            // MMAs on current buffer
        if (t + 1 < ntiles) {
            store_tile((t + 1) & 1);                    // fill the other buffer
            __syncthreads();                            // ONE barrier per tile
        }
    }

#pragma unroll
    for (int mi = 0; mi < 4; ++mi) {
        int r0 = bm * 128 + wm * 64 + mi * 16 + g;
#pragma unroll
        for (int ni = 0; ni < 4; ++ni) {
            int c = bn * 128 + wn * 32 + ni * 8 + 2 * tg;
            float b0 = 0.f, b1 = 0.f;
            if (bias) { b0 = bias[c]; b1 = bias[c + 1]; }
            float2 o0, o1;
            o0.x = acc[mi][ni][0] + b0; o0.y = acc[mi][ni][1] + b1;
            o1.x = acc[mi][ni][2] + b0; o1.y = acc[mi][ni][3] + b1;
            *(float2*)(C + (size_t)r0 * N + c)       = o0;
            *(float2*)(C + (size_t)(r0 + 8) * N + c) = o1;
        }
    }
}

// ---------------------------------------------------------------------------
// Neox RoPE applied in-place to x[T, nheads*128].
// ---------------------------------------------------------------------------
__global__ void rope_kernel(float* __restrict__ x, const int* __restrict__ positions,
                            int Ttot, int nheads)
{
    int idx = blockIdx.x * blockDim.x + threadIdx.x;
    int total = Ttot * nheads * (HD_ / 2);
    if (idx >= total) return;
    int i = idx & 63;
    int h = (idx >> 6) % nheads;
    int t = idx / (64 * nheads);

    int pos = positions[t % S_];
    float inv_freq = powf(10000.0f, -((float)(2 * i)) / (float)HD_);
    float freq = (float)pos * inv_freq;
    float s, c;
    sincosf(freq, &s, &c);

    size_t base = (size_t)t * (nheads * HD_) + h * HD_;
    float x1 = x[base + i];
    float x2 = x[base + 64 + i];
    x[base + i]      = x1 * c - x2 * s;
    x[base + 64 + i] = x2 * c + x1 * s;
}

// ---------------------------------------------------------------------------
// FP16 tensor-core flash attention (m16n8k16, causal, GQA rep=4).
// R11/R12 passing version: 256 threads, BM=128, BN=64.
// ---------------------------------------------------------------------------
#define QKW 68
#define VTW 36
#define FA_BM2 128

__global__ __launch_bounds__(256) void flash_attn_fp16_kernel(
    const float* __restrict__ Q, const float* __restrict__ K,
    const float* __restrict__ V, float* __restrict__ O)
{
    extern __shared__ uint32_t smu[];
    uint32_t* sQ  = smu;                        // 128*68
    uint32_t* sK  = sQ + FA_BM2 * QKW;          // 64*68
    uint32_t* sVt = sK + 64 * QKW;              // 128*36
    __half*   sVh = (__half*)sVt;               // halves, row stride 72

    const int qt = blockIdx.x;
    const int h  = blockIdx.y;
    const int b  = blockIdx.z;
    const int kvh = h >> 2;

    const int tid  = threadIdx.x;
    const int warp = tid >> 5;
    const int lane = tid & 31;
    const int g    = lane >> 2;   // 0..7
    const int tg   = lane & 3;    // 0..3
    const int q0   = qt * FA_BM2;
    const int w16  = warp * 16;

    const float* Qbase = Q + (size_t)b * S_ * (NH_ * HD_)  + h * HD_;
    const float* Kbase = K + (size_t)b * S_ * (NKV_ * HD_) + kvh * HD_;
    const float* Vbase = V + (size_t)b * S_ * (NKV_ * HD_) + kvh * HD_;

#pragma unroll 4
    for (int i = 0; i < 16; ++i) {
        int lin = i * 256 + tid;
        int r   = lin >> 5;
        int d4  = (lin & 31) * 4;
        float4 v = *(const float4*)(Qbase + (size_t)(q0 + r) * (NH_ * HD_) + d4);
        sQ[r * QKW + (d4 >> 1)]     = h2pack(v.x, v.y);
        sQ[r * QKW + (d4 >> 1) + 1] = h2pack(v.z, v.w);
    }

    float oacc[16][4];
#pragma unroll
    for (int n = 0; n < 16; ++n)
#pragma unroll
        for (int r = 0; r < 4; ++r) oacc[n][r] = 0.f;
    float m_i[2] = { -1e30f, -1e30f };
    float l_i[2] = { 0.f, 0.f };

    __syncthreads();

    const int njt = 2 * qt + 2;

    for (int j = 0; j < njt; ++j) {
        const int k0 = j * 64;

#pragma unroll 4
        for (int i = 0; i < 8; ++i) {
            int lin = i * 256 + tid;
            int r   = lin >> 5;
            int d4  = (lin & 31) * 4;
            float4 kv = *(const float4*)(Kbase + (size_t)(k0 + r) * (NKV_ * HD_) + d4);
            sK[r * QKW + (d4 >> 1)]     = h2pack(kv.x, kv.y);
            sK[r * QKW + (d4 >> 1) + 1] = h2pack(kv.z, kv.w);
        }
#pragma unroll 4
        for (int i = 0; i < 32; ++i) {
            int lin = i * 256 + tid;
            int dim = lin & 127;
            int r   = lin >> 7;
            float v = Vbase[(size_t)(k0 + r) * (NKV_ * HD_) + dim];
            sVh[dim * (2 * VTW) + r] = __float2half_rn(v);
        }
        __syncthreads();

        if (k0 <= q0 + w16 + 15) {
            float sacc[8][4];
#pragma unroll
            for (int n = 0; n < 8; ++n)
#pragma unroll
                for (int r = 0; r < 4; ++r) sacc[n][r] = 0.f;

#pragma unroll 2
            for (int ks = 0; ks < 8; ++ks) {
                uint32_t a[4];
                const int kc = ks * 8 + tg;
                a[0] = sQ[(w16 + g)     * QKW + kc];
                a[1] = sQ[(w16 + g + 8) * QKW + kc];
                a[2] = sQ[(w16 + g)     * QKW + kc + 4];
                a[3] = sQ[(w16 + g + 8) * QKW + kc + 4];
#pragma unroll
                for (int n = 0; n < 8; ++n) {
                    uint32_t bfr[2];
                    bfr[0] = sK[(n * 8 + g) * QKW + kc];
                    bfr[1] = sK[(n * 8 + g) * QKW + kc + 4];
                    mma_f16(sacc[n], a, bfr);
                }
            }

            const int r0g = q0 + w16 + g;
            const int r1g = r0g + 8;
            const bool diag = (k0 + 63 > q0 + w16);
#pragma unroll
            for (int n = 0; n < 8; ++n) {
                int cb = k0 + n * 8 + 2 * tg;
                float s0 = sacc[n][0] * SCALE_;
                float s1 = sacc[n][1] * SCALE_;
                float s2 = sacc[n][2] * SCALE_;
                float s3 = sacc[n][3] * SCALE_;
                if (diag) {
                    if (cb     > r0g) s0 = -1e30f;
                    if (cb + 1 > r0g) s1 = -1e30f;
                    if (cb     > r1g) s2 = -1e30f;
                    if (cb + 1 > r1g) s3 = -1e30f;
                }
                sacc[n][0] = s0; sacc[n][1] = s1; sacc[n][2] = s2; sacc[n][3] = s3;
            }

            float mx0 = -1e30f, mx1 = -1e30f;
#pragma unroll
            for (int n = 0; n < 8; ++n) {
                mx0 = fmaxf(mx0, fmaxf(sacc[n][0], sacc[n][1]));
                mx1 = fmaxf(mx1, fmaxf(sacc[n][2], sacc[n][3]));
            }
            mx0 = fmaxf(mx0, __shfl_xor_sync(0xffffffffu, mx0, 1));
            mx0 = fmaxf(mx0, __shfl_xor_sync(0xffffffffu, mx0, 2));
            mx1 = fmaxf(mx1, __shfl_xor_sync(0xffffffffu, mx1, 1));
            mx1 = fmaxf(mx1, __shfl_xor_sync(0xffffffffu, mx1, 2));

            float mn0 = fmaxf(m_i[0], mx0);
            float mn1 = fmaxf(m_i[1], mx1);
            float al0 = __expf(m_i[0] - mn0);
            float al1 = __expf(m_i[1] - mn1);
            m_i[0] = mn0; m_i[1] = mn1;

            uint32_t pk[8][2];
            float rs0 = 0.f, rs1 = 0.f;
#pragma unroll
            for (int n = 0; n < 8; ++n) {
                float p0 = __expf(sacc[n][0] - mn0);
                float p1 = __expf(sacc[n][1] - mn0);
                float p2 = __expf(sacc[n][2] - mn1);
                float p3 = __expf(sacc[n][3] - mn1);
                rs0 += p0 + p1;
                rs1 += p2 + p3;
                pk[n][0] = h2pack(p0, p1);
                pk[n][1] = h2pack(p2, p3);
            }
            rs0 += __shfl_xor_sync(0xffffffffu, rs0, 1);
            rs0 += __shfl_xor_sync(0xffffffffu, rs0, 2);
            rs1 += __shfl_xor_sync(0xffffffffu, rs1, 1);
            rs1 += __shfl_xor_sync(0xffffffffu, rs1, 2);
            l_i[0] = l_i[0] * al0 + rs0;
            l_i[1] = l_i[1] * al1 + rs1;

#pragma unroll
            for (int n = 0; n < 16; ++n) {
                oacc[n][0] *= al0; oacc[n][1] *= al0;
                oacc[n][2] *= al1; oacc[n][3] *= al1;
            }

#pragma unroll
            for (int ks = 0; ks < 4; ++ks) {
                uint32_t a[4];
                a[0] = pk[2 * ks][0];
                a[1] = pk[2 * ks][1];
                a[2] = pk[2 * ks + 1][0];
                a[3] = pk[2 * ks + 1][1];
                const int kc = ks * 8 + tg;
#pragma unroll 8
                for (int n = 0; n < 16; ++n) {
                    uint32_t bfr[2];
                    bfr[0] = sVt[(n * 8 + g) * VTW + kc];
                    bfr[1] = sVt[(n * 8 + g) * VTW + kc + 4];
                    mma_f16(oacc[n], a, bfr);
                }
            }
        }
        __syncthreads();
    }

    float inv0 = 1.0f / l_i[0];
    float inv1 = 1.0f / l_i[1];
    size_t t0 = (size_t)b * S_ + q0 + w16 + g;
    size_t t1 = t0 + 8;
    float* op0 = O + t0 * (NH_ * HD_) + h * HD_;
    float* op1 = O + t1 * (NH_ * HD_) + h * HD_;
#pragma unroll
    for (int n = 0; n < 16; ++n) {
        int c = n * 8 + 2 * tg;
        float2 v0, v1;
        v0.x = oacc[n][0] * inv0; v0.y = oacc[n][1] * inv0;
        v1.x = oacc[n][2] * inv1; v1.y = oacc[n][3] * inv1;
        *(float2*)(op0 + c) = v0;
        *(float2*)(op1 + c) = v1;
    }
}

// ---------------------------------------------------------------------------
// Launch
// ---------------------------------------------------------------------------
extern "C" void kernel_launch(void* const* d_in, const int* in_sizes, int n_in,
                              void* d_out, int out_size)
{
    const float* hidden = (const float*)d_in[0];
    const int*   positions = (const int*)d_in[1];
    const float* Wq = (const float*)d_in[2];
    const float* bq = (const float*)d_in[3];
    const float* Wk = (const float*)d_in[4];
    const float* bk = (const float*)d_in[5];
    const float* Wv = (const float*)d_in[6];
    const float* bv = (const float*)d_in[7];
    const float* Wo = (const float*)d_in[8];
    float* out = (float*)d_out;

    void *pQ, *pK, *pV, *pA;
    cudaGetSymbolAddress(&pQ, g_Q);
    cudaGetSymbolAddress(&pK, g_K);
    cudaGetSymbolAddress(&pV, g_V);
    cudaGetSymbolAddress(&pA, g_ATTN);
    float* Qs = (float*)pQ;
    float* Ks = (float*)pK;
    float* Vs = (float*)pV;
    float* As = (float*)pA;

    // QKV projections (split-fp16, 2-term, double-buffered)
    f16_gemm_kernel<true><<<dim3((NH_ * HD_) / 128, T_ / 128), 256>>>(hidden, Wq, bq, Qs, T_, NH_ * HD_, H_);
    f16_gemm_kernel<true><<<dim3((NKV_ * HD_) / 128, T_ / 128), 256>>>(hidden, Wk, bk, Ks, T_, NKV_ * HD_, H_);
    f16_gemm_kernel<true><<<dim3((NKV_ * HD_) / 128, T_ / 128), 256>>>(hidden, Wv, bv, Vs, T_, NKV_ * HD_, H_);

    // RoPE on Q and K
    {
        int totq = T_ * NH_ * 64;
        rope_kernel<<<(totq + 255) / 256, 256>>>(Qs, positions, T_, NH_);
        int totk = T_ * NKV_ * 64;
        rope_kernel<<<(totk + 255) / 256, 256>>>(Ks, positions, T_, NKV_);
    }

    // FP16 tensor-core flash attention (BM=128, BN=64, 8 warps)
    size_t fa_smem = (size_t)(FA_BM2 * QKW + 64 * QKW + FA_BM2 * VTW) * sizeof(uint32_t);
    cudaFuncSetAttribute(flash_attn_fp16_kernel, cudaFuncAttributeMaxDynamicSharedMemorySize, (int)fa_smem);
    flash_attn_fp16_kernel<<<dim3(S_ / FA_BM2, NH_, B_), 256, fa_smem>>>(Qs, Ks, Vs, As);

    // Output projection (plain fp16, 1-term, double-buffered)
    f16_gemm_kernel<false><<<dim3(H_ / 128, T_ / 128), 256>>>(As, Wo, nullptr, out, T_, H_, NH_ * HD_);
}

// round 16
// speedup vs baseline: 1.5567x; 1.0136x over previous
#include <cuda_runtime.h>
#include <cuda_bf16.h>
#include <cuda_fp16.h>
#include <math.h>
#include <stdint.h>

#define B_   2
#define S_   2048
#define H_   2048
#define NH_  16
#define NKV_ 4
#define HD_  128
#define T_   (B_ * S_)
#define SCALE_ 0.08838834764831845f

// ---------------------------------------------------------------------------
// Device scratch
// ---------------------------------------------------------------------------
__device__ uint32_t g_Ahi[T_ * (H_ / 2)];          // hidden hi pairs   16MB
__device__ uint32_t g_Alo[T_ * (H_ / 2)];          // hidden lo pairs   16MB
__device__ uint32_t g_Wq_p[(H_ / 2) * (NH_ * HD_)];   // 8MB
__device__ uint32_t g_Wk_p[(H_ / 2) * (NKV_ * HD_)];  // 2MB
__device__ uint32_t g_Wv_p[(H_ / 2) * (NKV_ * HD_)];  // 2MB
__device__ uint32_t g_Wo_p[((NH_ * HD_) / 2) * H_];   // 8MB
__device__ __half g_Qh[T_ * NH_ * HD_];
__device__ __half g_Kh[T_ * NKV_ * HD_];
__device__ __half g_Vh[T_ * NKV_ * HD_];
__device__ __half g_ATTNh[T_ * NH_ * HD_];

// ---------------------------------------------------------------------------
// Numeric helpers
// ---------------------------------------------------------------------------
__device__ __forceinline__ void mma_f16(float* d, const uint32_t* a, const uint32_t* b) {
    asm volatile(
        "mma.sync.aligned.m16n8k16.row.col.f32.f16.f16.f32 "
        "{%0,%1,%2,%3}, {%4,%5,%6,%7}, {%8,%9}, {%0,%1,%2,%3};"
        : "+f"(d[0]), "+f"(d[1]), "+f"(d[2]), "+f"(d[3])
        : "r"(a[0]), "r"(a[1]), "r"(a[2]), "r"(a[3]), "r"(b[0]), "r"(b[1]));
}
__device__ __forceinline__ void split_f16(float x, float& h, float& l) {
    __half hb = __float2half_rn(x);
    h = __half2float(hb);
    l = x - h;
}
__device__ __forceinline__ uint32_t h2pack(float x, float y) {
    __half2 t = __floats2half2_rn(x, y);
    return *reinterpret_cast<uint32_t*>(&t);
}

// ---------------------------------------------------------------------------
// Prepass: pack hidden into hi/lo half2-pair words (pairs along K)
// ---------------------------------------------------------------------------
__global__ void pack_A_kernel(const float* __restrict__ x,
                              uint32_t* __restrict__ hi, uint32_t* __restrict__ lo,
                              int nwords)
{
    int idx = blockIdx.x * blockDim.x + threadIdx.x;
    if (idx >= nwords) return;
    float2 v = ((const float2*)x)[idx];
    float hx, lx, hy, ly;
    split_f16(v.x, hx, lx);
    split_f16(v.y, hy, ly);
    hi[idx] = h2pack(hx, hy);
    lo[idx] = h2pack(lx, ly);
}

// Prepass: pack W[K][N] -> out[k2][n] = (W[2k2][n], W[2k2+1][n])
__global__ void pack_W_kernel(const float* __restrict__ W, uint32_t* __restrict__ out,
                              int K2, int N)
{
    int idx = blockIdx.x * blockDim.x + threadIdx.x;
    if (idx >= K2 * N) return;
    int k2 = idx / N, n = idx - k2 * N;
    float a = W[(size_t)(2 * k2) * N + n];
    float b = W[(size_t)(2 * k2 + 1) * N + n];
    out[idx] = h2pack(a, b);
}

// ---------------------------------------------------------------------------
// Packed FP16 GEMM. TWO: C_half = (Ahi+Alo)*B ; !TWO: C_float = Ahi*B.
// A: [M][K/2] u32 pair-words. B: [K/2][N] u32 pair-words.
// Tile 128x128x16; 256 threads (8 warps 2x4, warp tile 64x32); double-buffered.
// ---------------------------------------------------------------------------
#define GA_STR 12
#define GA_TILE (128 * GA_STR)
#define GBT_STR 136
#define GBT_TILE (8 * GBT_STR)

template<bool TWO>
__global__ __launch_bounds__(256) void f16_gemm_packed(
    const uint32_t* __restrict__ Ahi, const uint32_t* __restrict__ Alo,
    const uint32_t* __restrict__ Bp, const float* __restrict__ bias,
    void* __restrict__ Cout, int M, int N, int K)
{
    __shared__ uint32_t Ahs[2][GA_TILE];
    __shared__ uint32_t Als[TWO ? 2 : 1][TWO ? GA_TILE : 32];
    __shared__ uint32_t Bts[2][GBT_TILE];

    const int tid  = threadIdx.x;
    const int warp = tid >> 5;
    const int lane = tid & 31;
    const int g    = lane >> 2;
    const int tg   = lane & 3;
    const int wm   = warp >> 2;
    const int wn   = warp & 3;

    const int bm = blockIdx.y;
    const int bn = blockIdx.x;
    const int K2 = K >> 1;

    const uint32_t* Abase  = Ahi + (size_t)(bm * 128) * K2;
    const uint32_t* Albase = TWO ? (Alo + (size_t)(bm * 128) * K2) : nullptr;

    // staging indices (per thread): A row = tid>>1, quad = tid&1 ; B row = tid>>5, quad = tid&31
    const int ar = tid >> 1, aq = (tid & 1) * 4;
    const int br = tid >> 5, bq = (tid & 31) * 4;

    float acc[4][4][4];
#pragma unroll
    for (int mi = 0; mi < 4; ++mi)
#pragma unroll
        for (int ni = 0; ni < 4; ++ni)
#pragma unroll
            for (int r = 0; r < 4; ++r) acc[mi][ni][r] = 0.f;

    uint4 aR, alR, bR;
    auto load_tile = [&](int t) {
        int k2 = t * 8;
        aR = *(const uint4*)(Abase + (size_t)ar * K2 + k2 + aq);
        if (TWO) alR = *(const uint4*)(Albase + (size_t)ar * K2 + k2 + aq);
        bR = *(const uint4*)(Bp + (size_t)(k2 + br) * N + bn * 128 + bq);
    };
    auto store_tile = [&](int buf) {
        *(uint4*)&Ahs[buf][ar * GA_STR + aq] = aR;
        if (TWO) *(uint4*)&Als[buf][ar * GA_STR + aq] = alR;
        *(uint4*)&Bts[buf][br * GBT_STR + bq] = bR;
    };
    auto compute_tile = [&](int buf) {
        uint32_t ah[4][4], al[4][4];
        uint32_t bh[4][2];
#pragma unroll
        for (int mi = 0; mi < 4; ++mi) {
            int r0 = (wm * 64 + mi * 16 + g) * GA_STR;
            ah[mi][0] = Ahs[buf][r0 + tg];
            ah[mi][1] = Ahs[buf][r0 + 8 * GA_STR + tg];
            ah[mi][2] = Ahs[buf][r0 + tg + 4];
            ah[mi][3] = Ahs[buf][r0 + 8 * GA_STR + tg + 4];
            if (TWO) {
                al[mi][0] = Als[buf][r0 + tg];
                al[mi][1] = Als[buf][r0 + 8 * GA_STR + tg];
                al[mi][2] = Als[buf][r0 + tg + 4];
                al[mi][3] = Als[buf][r0 + 8 * GA_STR + tg + 4];
            }
        }
#pragma unroll
        for (int ni = 0; ni < 4; ++ni) {
            int n0 = wn * 32 + ni * 8 + g;
            bh[ni][0] = Bts[buf][tg * GBT_STR + n0];
            bh[ni][1] = Bts[buf][(tg + 4) * GBT_STR + n0];
        }
#pragma unroll
        for (int mi = 0; mi < 4; ++mi)
#pragma unroll
            for (int ni = 0; ni < 4; ++ni) {
                mma_f16(acc[mi][ni], ah[mi], bh[ni]);
                if (TWO) mma_f16(acc[mi][ni], al[mi], bh[ni]);
            }
    };

    const int ntiles = K / 16;

    load_tile(0);
    store_tile(0);
    __syncthreads();

    for (int t = 0; t < ntiles; ++t) {
        if (t + 1 < ntiles) load_tile(t + 1);
        compute_tile(t & 1);
        if (t + 1 < ntiles) {
            store_tile((t + 1) & 1);
            __syncthreads();
        }
    }

    if (TWO) {
        __half* Ch = (__half*)Cout;
#pragma unroll
        for (int mi = 0; mi < 4; ++mi) {
            int r0 = bm * 128 + wm * 64 + mi * 16 + g;
#pragma unroll
            for (int ni = 0; ni < 4; ++ni) {
                int c = bn * 128 + wn * 32 + ni * 8 + 2 * tg;
                float b0 = bias ? bias[c] : 0.f;
                float b1 = bias ? bias[c + 1] : 0.f;
                *(uint32_t*)(Ch + (size_t)r0 * N + c) =
                    h2pack(acc[mi][ni][0] + b0, acc[mi][ni][1] + b1);
                *(uint32_t*)(Ch + (size_t)(r0 + 8) * N + c) =
                    h2pack(acc[mi][ni][2] + b0, acc[mi][ni][3] + b1);
            }
        }
    } else {
        float* Cf = (float*)Cout;
#pragma unroll
        for (int mi = 0; mi < 4; ++mi) {
            int r0 = bm * 128 + wm * 64 + mi * 16 + g;
#pragma unroll
            for (int ni = 0; ni < 4; ++ni) {
                int c = bn * 128 + wn * 32 + ni * 8 + 2 * tg;
                float2 o0, o1;
                o0.x = acc[mi][ni][0]; o0.y = acc[mi][ni][1];
                o1.x = acc[mi][ni][2]; o1.y = acc[mi][ni][3];
                *(float2*)(Cf + (size_t)r0 * N + c)       = o0;
                *(float2*)(Cf + (size_t)(r0 + 8) * N + c) = o1;
            }
        }
    }
}

// ---------------------------------------------------------------------------
// Neox RoPE in-place on half array x[T, nheads*128].
// ---------------------------------------------------------------------------
__global__ void rope_h_kernel(__half* __restrict__ x, const int* __restrict__ positions,
                              int Ttot, int nheads)
{
    int idx = blockIdx.x * blockDim.x + threadIdx.x;
    int total = Ttot * nheads * (HD_ / 2);
    if (idx >= total) return;
    int i = idx & 63;
    int h = (idx >> 6) % nheads;
    int t = idx / (64 * nheads);

    int pos = positions[t % S_];
    float inv_freq = powf(10000.0f, -((float)(2 * i)) / (float)HD_);
    float freq = (float)pos * inv_freq;
    float s, c;
    sincosf(freq, &s, &c);

    size_t base = (size_t)t * (nheads * HD_) + h * HD_;
    float x1 = __half2float(x[base + i]);
    float x2 = __half2float(x[base + 64 + i]);
    x[base + i]      = __float2half_rn(x1 * c - x2 * s);
    x[base + 64 + i] = __float2half_rn(x2 * c + x1 * s);
}

// ---------------------------------------------------------------------------
// FP16 flash attention on half inputs (m16n8k16, causal, GQA rep=4).
// 256 threads, BM=128, BN=64. All staging is copies/byte-perms (no converts).
// ---------------------------------------------------------------------------
#define QKW 68
#define VTW 36
#define FA_BM2 128

__global__ __launch_bounds__(256) void flash_attn_fp16_kernel(
    const __half* __restrict__ Q, const __half* __restrict__ K,
    const __half* __restrict__ V, __half* __restrict__ O)
{
    extern __shared__ uint32_t smu[];
    uint32_t* sQ  = smu;                        // 128*68
    uint32_t* sK  = sQ + FA_BM2 * QKW;          // 64*68
    uint32_t* sVt = sK + 64 * QKW;              // 128*36

    const int qt = blockIdx.x;
    const int h  = blockIdx.y;
    const int b  = blockIdx.z;
    const int kvh = h >> 2;

    const int tid  = threadIdx.x;
    const int warp = tid >> 5;
    const int lane = tid & 31;
    const int g    = lane >> 2;
    const int tg   = lane & 3;
    const int q0   = qt * FA_BM2;
    const int w16  = warp * 16;

    const __half* Qbase = Q + (size_t)b * S_ * (NH_ * HD_)  + h * HD_;
    const __half* Kbase = K + (size_t)b * S_ * (NKV_ * HD_) + kvh * HD_;
    const __half* Vbase = V + (size_t)b * S_ * (NKV_ * HD_) + kvh * HD_;

    // Q tile: 128 rows x 64 words; uint4 copies
#pragma unroll
    for (int i = 0; i < 8; ++i) {
        int p = i * 256 + tid;
        int r = p >> 4, q = p & 15;
        uint4 v = *(const uint4*)(Qbase + (size_t)(q0 + r) * (NH_ * HD_) + q * 8);
        *(uint4*)&sQ[r * QKW + q * 4] = v;
    }

    float oacc[16][4];
#pragma unroll
    for (int n = 0; n < 16; ++n)
#pragma unroll
        for (int r = 0; r < 4; ++r) oacc[n][r] = 0.f;
    float m_i[2] = { -1e30f, -1e30f };
    float l_i[2] = { 0.f, 0.f };

    __syncthreads();

    const int njt = 2 * qt + 2;

    for (int j = 0; j < njt; ++j) {
        const int k0 = j * 64;

        // K tile: 64 rows x 64 words
#pragma unroll
        for (int i = 0; i < 4; ++i) {
            int p = i * 256 + tid;
            int r = p >> 4, q = p & 15;
            uint4 v = *(const uint4*)(Kbase + (size_t)(k0 + r) * (NKV_ * HD_) + q * 8);
            *(uint4*)&sK[r * QKW + q * 4] = v;
        }
        // V transposed: (r2, d2) -> sVt[2d2][r2], sVt[2d2+1][r2]
#pragma unroll
        for (int i = 0; i < 8; ++i) {
            int p  = i * 256 + tid;
            int r2 = p & 31;          // kv pair 0..31
            int d2 = p >> 5;          // dim pair 0..63
            uint32_t w0 = *(const uint32_t*)(Vbase + (size_t)(k0 + 2 * r2)     * (NKV_ * HD_) + 2 * d2);
            uint32_t w1 = *(const uint32_t*)(Vbase + (size_t)(k0 + 2 * r2 + 1) * (NKV_ * HD_) + 2 * d2);
            sVt[(2 * d2)     * VTW + r2] = __byte_perm(w0, w1, 0x5410);
            sVt[(2 * d2 + 1) * VTW + r2] = __byte_perm(w0, w1, 0x7632);
        }
        __syncthreads();

        if (k0 <= q0 + w16 + 15) {
            float sacc[8][4];
#pragma unroll
            for (int n = 0; n < 8; ++n)
#pragma unroll
                for (int r = 0; r < 4; ++r) sacc[n][r] = 0.f;

#pragma unroll 2
            for (int ks = 0; ks < 8; ++ks) {
                uint32_t a[4];
                const int kc = ks * 8 + tg;
                a[0] = sQ[(w16 + g)     * QKW + kc];
                a[1] = sQ[(w16 + g + 8) * QKW + kc];
                a[2] = sQ[(w16 + g)     * QKW + kc + 4];
                a[3] = sQ[(w16 + g + 8) * QKW + kc + 4];
#pragma unroll
                for (int n = 0; n < 8; ++n) {
                    uint32_t bfr[2];
                    bfr[0] = sK[(n * 8 + g) * QKW + kc];
                    bfr[1] = sK[(n * 8 + g) * QKW + kc + 4];
                    mma_f16(sacc[n], a, bfr);
                }
            }

            const int r0g = q0 + w16 + g;
            const int r1g = r0g + 8;
            const bool diag = (k0 + 63 > q0 + w16);
#pragma unroll
            for (int n = 0; n < 8; ++n) {
                int cb = k0 + n * 8 + 2 * tg;
                float s0 = sacc[n][0] * SCALE_;
                float s1 = sacc[n][1] * SCALE_;
                float s2 = sacc[n][2] * SCALE_;
                float s3 = sacc[n][3] * SCALE_;
                if (diag) {
                    if (cb     > r0g) s0 = -1e30f;
                    if (cb + 1 > r0g) s1 = -1e30f;
                    if (cb     > r1g) s2 = -1e30f;
                    if (cb + 1 > r1g) s3 = -1e30f;
                }
                sacc[n][0] = s0; sacc[n][1] = s1; sacc[n][2] = s2; sacc[n][3] = s3;
            }

            float mx0 = -1e30f, mx1 = -1e30f;
#pragma unroll
            for (int n = 0; n < 8; ++n) {
                mx0 = fmaxf(mx0, fmaxf(sacc[n][0], sacc[n][1]));
                mx1 = fmaxf(mx1, fmaxf(sacc[n][2], sacc[n][3]));
            }
            mx0 = fmaxf(mx0, __shfl_xor_sync(0xffffffffu, mx0, 1));
            mx0 = fmaxf(mx0, __shfl_xor_sync(0xffffffffu, mx0, 2));
            mx1 = fmaxf(mx1, __shfl_xor_sync(0xffffffffu, mx1, 1));
            mx1 = fmaxf(mx1, __shfl_xor_sync(0xffffffffu, mx1, 2));

            float mn0 = fmaxf(m_i[0], mx0);
            float mn1 = fmaxf(m_i[1], mx1);
            float al0 = __expf(m_i[0] - mn0);
            float al1 = __expf(m_i[1] - mn1);
            m_i[0] = mn0; m_i[1] = mn1;

            uint32_t pk[8][2];
            float rs0 = 0.f, rs1 = 0.f;
#pragma unroll
            for (int n = 0; n < 8; ++n) {
                float p0 = __expf(sacc[n][0] - mn0);
                float p1 = __expf(sacc[n][1] - mn0);
                float p2 = __expf(sacc[n][2] - mn1);
                float p3 = __expf(sacc[n][3] - mn1);
                rs0 += p0 + p1;
                rs1 += p2 + p3;
                pk[n][0] = h2pack(p0, p1);
                pk[n][1] = h2pack(p2, p3);
            }
            rs0 += __shfl_xor_sync(0xffffffffu, rs0, 1);
            rs0 += __shfl_xor_sync(0xffffffffu, rs0, 2);
            rs1 += __shfl_xor_sync(0xffffffffu, rs1, 1);
            rs1 += __shfl_xor_sync(0xffffffffu, rs1, 2);
            l_i[0] = l_i[0] * al0 + rs0;
            l_i[1] = l_i[1] * al1 + rs1;

#pragma unroll
            for (int n = 0; n < 16; ++n) {
                oacc[n][0] *= al0; oacc[n][1] *= al0;
                oacc[n][2] *= al1; oacc[n][3] *= al1;
            }

#pragma unroll
            for (int ks = 0; ks < 4; ++ks) {
                uint32_t a[4];
                a[0] = pk[2 * ks][0];
                a[1] = pk[2 * ks][1];
                a[2] = pk[2 * ks + 1][0];
                a[3] = pk[2 * ks + 1][1];
                const int kc = ks * 8 + tg;
#pragma unroll 8
                for (int n = 0; n < 16; ++n) {
                    uint32_t bfr[2];
                    bfr[0] = sVt[(n * 8 + g) * VTW + kc];
                    bfr[1] = sVt[(n * 8 + g) * VTW + kc + 4];
                    mma_f16(oacc[n], a, bfr);
                }
            }
        }
        __syncthreads();
    }

    float inv0 = 1.0f / l_i[0];
    float inv1 = 1.0f / l_i[1];
    size_t t0 = (size_t)b * S_ + q0 + w16 + g;
    size_t t1 = t0 + 8;
    __half* op0 = O + t0 * (NH_ * HD_) + h * HD_;
    __half* op1 = O + t1 * (NH_ * HD_) + h * HD_;
#pragma unroll
    for (int n = 0; n < 16; ++n) {
        int c = n * 8 + 2 * tg;
        *(uint32_t*)(op0 + c) = h2pack(oacc[n][0] * inv0, oacc[n][1] * inv0);
        *(uint32_t*)(op1 + c) = h2pack(oacc[n][2] * inv1, oacc[n][3] * inv1);
    }
}

// ---------------------------------------------------------------------------
// Launch
// ---------------------------------------------------------------------------
extern "C" void kernel_launch(void* const* d_in, const int* in_sizes, int n_in,
                              void* d_out, int out_size)
{
    const float* hidden = (const float*)d_in[0];
    const int*   positions = (const int*)d_in[1];
    const float* Wq = (const float*)d_in[2];
    const float* bq = (const float*)d_in[3];
    const float* Wk = (const float*)d_in[4];
    const float* bk = (const float*)d_in[5];
    const float* Wv = (const float*)d_in[6];
    const float* bv = (const float*)d_in[7];
    const float* Wo = (const float*)d_in[8];
    float* out = (float*)d_out;

    void *pAhi, *pAlo, *pWq, *pWk, *pWv, *pWo, *pQ, *pK, *pV, *pA;
    cudaGetSymbolAddress(&pAhi, g_Ahi);
    cudaGetSymbolAddress(&pAlo, g_Alo);
    cudaGetSymbolAddress(&pWq, g_Wq_p);
    cudaGetSymbolAddress(&pWk, g_Wk_p);
    cudaGetSymbolAddress(&pWv, g_Wv_p);
    cudaGetSymbolAddress(&pWo, g_Wo_p);
    cudaGetSymbolAddress(&pQ, g_Qh);
    cudaGetSymbolAddress(&pK, g_Kh);
    cudaGetSymbolAddress(&pV, g_Vh);
    cudaGetSymbolAddress(&pA, g_ATTNh);

    uint32_t* Ahi = (uint32_t*)pAhi;
    uint32_t* Alo = (uint32_t*)pAlo;
    uint32_t* Wqp = (uint32_t*)pWq;
    uint32_t* Wkp = (uint32_t*)pWk;
    uint32_t* Wvp = (uint32_t*)pWv;
    uint32_t* Wop = (uint32_t*)pWo;
    __half* Qh = (__half*)pQ;
    __half* Kh = (__half*)pK;
    __half* Vh = (__half*)pV;
    __half* Ah = (__half*)pA;

    // Prepass packs
    {
        int nwA = T_ * (H_ / 2);
        pack_A_kernel<<<(nwA + 255) / 256, 256>>>(hidden, Ahi, Alo, nwA);
        int nq = (H_ / 2) * (NH_ * HD_);
        pack_W_kernel<<<(nq + 255) / 256, 256>>>(Wq, Wqp, H_ / 2, NH_ * HD_);
        int nk = (H_ / 2) * (NKV_ * HD_);
        pack_W_kernel<<<(nk + 255) / 256, 256>>>(Wk, Wkp, H_ / 2, NKV_ * HD_);
        pack_W_kernel<<<(nk + 255) / 256, 256>>>(Wv, Wvp, H_ / 2, NKV_ * HD_);
        int no = ((NH_ * HD_) / 2) * H_;
        pack_W_kernel<<<(no + 255) / 256, 256>>>(Wo, Wop, (NH_ * HD_) / 2, H_);
    }

    // QKV projections (2-term, half output)
    f16_gemm_packed<true><<<dim3((NH_ * HD_) / 128, T_ / 128), 256>>>(Ahi, Alo, Wqp, bq, Qh, T_, NH_ * HD_, H_);
    f16_gemm_packed<true><<<dim3((NKV_ * HD_) / 128, T_ / 128), 256>>>(Ahi, Alo, Wkp, bk, Kh, T_, NKV_ * HD_, H_);
    f16_gemm_packed<true><<<dim3((NKV_ * HD_) / 128, T_ / 128), 256>>>(Ahi, Alo, Wvp, bv, Vh, T_, NKV_ * HD_, H_);

    // RoPE on half Q/K
    {
        int totq = T_ * NH_ * 64;
        rope_h_kernel<<<(totq + 255) / 256, 256>>>(Qh, positions, T_, NH_);
        int totk = T_ * NKV_ * 64;
        rope_h_kernel<<<(totk + 255) / 256, 256>>>(Kh, positions, T_, NKV_);
    }

    // Flash attention (half in/out)
    size_t fa_smem = (size_t)(FA_BM2 * QKW + 64 * QKW + FA_BM2 * VTW) * sizeof(uint32_t);
    cudaFuncSetAttribute(flash_attn_fp16_kernel, cudaFuncAttributeMaxDynamicSharedMemorySize, (int)fa_smem);
    flash_attn_fp16_kernel<<<dim3(S_ / FA_BM2, NH_, B_), 256, fa_smem>>>(Qh, Kh, Vh, Ah);

    // Output projection (1-term: A = attention halves directly, float out)
    f16_gemm_packed<false><<<dim3(H_ / 128, T_ / 128), 256>>>(
        (const uint32_t*)Ah, nullptr, Wop, nullptr, out, T_, H_, NH_ * HD_);
}

// round 17
// speedup vs baseline: 1.7583x; 1.1295x over previous
#include <cuda_runtime.h>
#include <cuda_bf16.h>
#include <cuda_fp16.h>
#include <math.h>
#include <stdint.h>

#define B_   2
#define S_   2048
#define H_   2048
#define NH_  16
#define NKV_ 4
#define HD_  128
#define T_   (B_ * S_)
#define SCALE_ 0.08838834764831845f

// ---------------------------------------------------------------------------
// Device scratch
// ---------------------------------------------------------------------------
__device__ uint32_t g_Ahi[T_ * (H_ / 2)];
__device__ uint32_t g_Alo[T_ * (H_ / 2)];
__device__ uint32_t g_Wq_p[(H_ / 2) * (NH_ * HD_)];
__device__ uint32_t g_Wk_p[(H_ / 2) * (NKV_ * HD_)];
__device__ uint32_t g_Wv_p[(H_ / 2) * (NKV_ * HD_)];
__device__ uint32_t g_Wo_p[((NH_ * HD_) / 2) * H_];
__device__ __half g_Qh[T_ * NH_ * HD_];
__device__ __half g_Kh[T_ * NKV_ * HD_];
__device__ __half g_Vh[T_ * NKV_ * HD_];
__device__ __half g_ATTNh[T_ * NH_ * HD_];

// ---------------------------------------------------------------------------
// Numeric / MMA / ldmatrix helpers
// ---------------------------------------------------------------------------
__device__ __forceinline__ void mma_f16(float* d, const uint32_t* a, const uint32_t* b) {
    asm volatile(
        "mma.sync.aligned.m16n8k16.row.col.f32.f16.f16.f32 "
        "{%0,%1,%2,%3}, {%4,%5,%6,%7}, {%8,%9}, {%0,%1,%2,%3};"
        : "+f"(d[0]), "+f"(d[1]), "+f"(d[2]), "+f"(d[3])
        : "r"(a[0]), "r"(a[1]), "r"(a[2]), "r"(a[3]), "r"(b[0]), "r"(b[1]));
}
__device__ __forceinline__ void ldsm_x4(uint32_t& r0, uint32_t& r1, uint32_t& r2, uint32_t& r3,
                                        uint32_t saddr) {
    asm volatile("ldmatrix.sync.aligned.m8n8.x4.shared.b16 {%0,%1,%2,%3}, [%4];"
                 : "=r"(r0), "=r"(r1), "=r"(r2), "=r"(r3) : "r"(saddr));
}
__device__ __forceinline__ void ldsm_x4_t(uint32_t& r0, uint32_t& r1, uint32_t& r2, uint32_t& r3,
                                          uint32_t saddr) {
    asm volatile("ldmatrix.sync.aligned.m8n8.x4.trans.shared.b16 {%0,%1,%2,%3}, [%4];"
                 : "=r"(r0), "=r"(r1), "=r"(r2), "=r"(r3) : "r"(saddr));
}
__device__ __forceinline__ void split_f16(float x, float& h, float& l) {
    __half hb = __float2half_rn(x);
    h = __half2float(hb);
    l = x - h;
}
__device__ __forceinline__ uint32_t h2pack(float x, float y) {
    __half2 t = __floats2half2_rn(x, y);
    return *reinterpret_cast<uint32_t*>(&t);
}

// ---------------------------------------------------------------------------
// Prepass packs
// ---------------------------------------------------------------------------
__global__ void pack_A_kernel(const float* __restrict__ x,
                              uint32_t* __restrict__ hi, uint32_t* __restrict__ lo,
                              int nwords)
{
    int idx = blockIdx.x * blockDim.x + threadIdx.x;
    if (idx >= nwords) return;
    float2 v = ((const float2*)x)[idx];
    float hx, lx, hy, ly;
    split_f16(v.x, hx, lx);
    split_f16(v.y, hy, ly);
    hi[idx] = h2pack(hx, hy);
    lo[idx] = h2pack(lx, ly);
}

__global__ void pack_W_kernel(const float* __restrict__ W, uint32_t* __restrict__ out,
                              int K2, int N)
{
    int idx = blockIdx.x * blockDim.x + threadIdx.x;
    if (idx >= K2 * N) return;
    int k2 = idx / N, n = idx - k2 * N;
    float a = W[(size_t)(2 * k2) * N + n];
    float b = W[(size_t)(2 * k2 + 1) * N + n];
    out[idx] = h2pack(a, b);
}

// ---------------------------------------------------------------------------
// Packed FP16 GEMM (A-frags via ldmatrix). TWO: C_half=(Ahi+Alo)*B; !TWO: C_float=Ahi*B.
// ---------------------------------------------------------------------------
#define GA_STR 12
#define GA_TILE (128 * GA_STR)
#define GBT_STR 136
#define GBT_TILE (8 * GBT_STR)

template<bool TWO>
__global__ __launch_bounds__(256) void f16_gemm_packed(
    const uint32_t* __restrict__ Ahi, const uint32_t* __restrict__ Alo,
    const uint32_t* __restrict__ Bp, const float* __restrict__ bias,
    void* __restrict__ Cout, int M, int N, int K)
{
    __shared__ __align__(16) uint32_t Ahs[2][GA_TILE];
    __shared__ __align__(16) uint32_t Als[TWO ? 2 : 1][TWO ? GA_TILE : 32];
    __shared__ __align__(16) uint32_t Bts[2][GBT_TILE];

    const int tid  = threadIdx.x;
    const int warp = tid >> 5;
    const int lane = tid & 31;
    const int g    = lane >> 2;
    const int tg   = lane & 3;
    const int wm   = warp >> 2;
    const int wn   = warp & 3;

    const int bm = blockIdx.y;
    const int bn = blockIdx.x;
    const int K2 = K >> 1;

    const uint32_t* Abase  = Ahi + (size_t)(bm * 128) * K2;
    const uint32_t* Albase = TWO ? (Alo + (size_t)(bm * 128) * K2) : nullptr;

    const int ar = tid >> 1, aq = (tid & 1) * 4;
    const int br = tid >> 5, bq = (tid & 31) * 4;

    // ldmatrix per-lane base (bytes) within an A tile buffer
    const uint32_t Alm = (uint32_t)(((lane & 15) * GA_STR + (lane >> 4) * 4) * 4);
    const uint32_t AhsA0 = (uint32_t)__cvta_generic_to_shared(&Ahs[0][0]);
    const uint32_t AhsA1 = (uint32_t)__cvta_generic_to_shared(&Ahs[1][0]);
    const uint32_t AlsA0 = (uint32_t)__cvta_generic_to_shared(&Als[0][0]);
    const uint32_t AlsA1 = TWO ? (uint32_t)__cvta_generic_to_shared(&Als[1][0]) : 0;

    float acc[4][4][4];
#pragma unroll
    for (int mi = 0; mi < 4; ++mi)
#pragma unroll
        for (int ni = 0; ni < 4; ++ni)
#pragma unroll
            for (int r = 0; r < 4; ++r) acc[mi][ni][r] = 0.f;

    uint4 aR, alR, bR;
    auto load_tile = [&](int t) {
        int k2 = t * 8;
        aR = *(const uint4*)(Abase + (size_t)ar * K2 + k2 + aq);
        if (TWO) alR = *(const uint4*)(Albase + (size_t)ar * K2 + k2 + aq);
        bR = *(const uint4*)(Bp + (size_t)(k2 + br) * N + bn * 128 + bq);
    };
    auto store_tile = [&](int buf) {
        *(uint4*)&Ahs[buf][ar * GA_STR + aq] = aR;
        if (TWO) *(uint4*)&Als[buf][ar * GA_STR + aq] = alR;
        *(uint4*)&Bts[buf][br * GBT_STR + bq] = bR;
    };
    auto compute_tile = [&](int buf) {
        const uint32_t ahA = (buf ? AhsA1 : AhsA0) + Alm;
        const uint32_t alA = TWO ? ((buf ? AlsA1 : AlsA0) + Alm) : 0;
        uint32_t ah[4][4], al[4][4];
        uint32_t bh[4][2];
#pragma unroll
        for (int mi = 0; mi < 4; ++mi) {
            uint32_t off = (uint32_t)((wm * 64 + mi * 16) * GA_STR * 4);
            ldsm_x4(ah[mi][0], ah[mi][1], ah[mi][2], ah[mi][3], ahA + off);
            if (TWO) ldsm_x4(al[mi][0], al[mi][1], al[mi][2], al[mi][3], alA + off);
        }
#pragma unroll
        for (int ni = 0; ni < 4; ++ni) {
            int n0 = wn * 32 + ni * 8 + g;
            bh[ni][0] = Bts[buf][tg * GBT_STR + n0];
            bh[ni][1] = Bts[buf][(tg + 4) * GBT_STR + n0];
        }
#pragma unroll
        for (int mi = 0; mi < 4; ++mi)
#pragma unroll
            for (int ni = 0; ni < 4; ++ni) {
                mma_f16(acc[mi][ni], ah[mi], bh[ni]);
                if (TWO) mma_f16(acc[mi][ni], al[mi], bh[ni]);
            }
    };

    const int ntiles = K / 16;

    load_tile(0);
    store_tile(0);
    __syncthreads();

    for (int t = 0; t < ntiles; ++t) {
        if (t + 1 < ntiles) load_tile(t + 1);
        compute_tile(t & 1);
        if (t + 1 < ntiles) {
            store_tile((t + 1) & 1);
            __syncthreads();
        }
    }

    if (TWO) {
        __half* Ch = (__half*)Cout;
#pragma unroll
        for (int mi = 0; mi < 4; ++mi) {
            int r0 = bm * 128 + wm * 64 + mi * 16 + g;
#pragma unroll
            for (int ni = 0; ni < 4; ++ni) {
                int c = bn * 128 + wn * 32 + ni * 8 + 2 * tg;
                float b0 = bias ? bias[c] : 0.f;
                float b1 = bias ? bias[c + 1] : 0.f;
                *(uint32_t*)(Ch + (size_t)r0 * N + c) =
                    h2pack(acc[mi][ni][0] + b0, acc[mi][ni][1] + b1);
                *(uint32_t*)(Ch + (size_t)(r0 + 8) * N + c) =
                    h2pack(acc[mi][ni][2] + b0, acc[mi][ni][3] + b1);
            }
        }
    } else {
        float* Cf = (float*)Cout;
#pragma unroll
        for (int mi = 0; mi < 4; ++mi) {
            int r0 = bm * 128 + wm * 64 + mi * 16 + g;
#pragma unroll
            for (int ni = 0; ni < 4; ++ni) {
                int c = bn * 128 + wn * 32 + ni * 8 + 2 * tg;
                float2 o0, o1;
                o0.x = acc[mi][ni][0]; o0.y = acc[mi][ni][1];
                o1.x = acc[mi][ni][2]; o1.y = acc[mi][ni][3];
                *(float2*)(Cf + (size_t)r0 * N + c)       = o0;
                *(float2*)(Cf + (size_t)(r0 + 8) * N + c) = o1;
            }
        }
    }
}

// ---------------------------------------------------------------------------
// Neox RoPE in-place on half array x[T, nheads*128].
// ---------------------------------------------------------------------------
__global__ void rope_h_kernel(__half* __restrict__ x, const int* __restrict__ positions,
                              int Ttot, int nheads)
{
    int idx = blockIdx.x * blockDim.x + threadIdx.x;
    int total = Ttot * nheads * (HD_ / 2);
    if (idx >= total) return;
    int i = idx & 63;
    int h = (idx >> 6) % nheads;
    int t = idx / (64 * nheads);

    int pos = positions[t % S_];
    float inv_freq = powf(10000.0f, -((float)(2 * i)) / (float)HD_);
    float freq = (float)pos * inv_freq;
    float s, c;
    sincosf(freq, &s, &c);

    size_t base = (size_t)t * (nheads * HD_) + h * HD_;
    float x1 = __half2float(x[base + i]);
    float x2 = __half2float(x[base + 64 + i]);
    x[base + i]      = __float2half_rn(x1 * c - x2 * s);
    x[base + 64 + i] = __float2half_rn(x2 * c + x1 * s);
}

// ---------------------------------------------------------------------------
// FP16 flash attention, ldmatrix fragment feeds. BM=128, BN=64, 256 threads.
// sQ[128][68w], sK[64][68w], sV[64][68w] (V row-major; trans at consume).
// ---------------------------------------------------------------------------
#define QKW 68
#define FA_BM2 128

__global__ __launch_bounds__(256) void flash_attn_fp16_kernel(
    const __half* __restrict__ Q, const __half* __restrict__ K,
    const __half* __restrict__ V, __half* __restrict__ O)
{
    extern __shared__ uint32_t smu[];
    uint32_t* sQ = smu;                        // 128*68
    uint32_t* sK = sQ + FA_BM2 * QKW;          // 64*68
    uint32_t* sV = sK + 64 * QKW;              // 64*68

    const int qt = blockIdx.x;
    const int h  = blockIdx.y;
    const int b  = blockIdx.z;
    const int kvh = h >> 2;

    const int tid  = threadIdx.x;
    const int warp = tid >> 5;
    const int lane = tid & 31;
    const int q0   = qt * FA_BM2;
    const int w16  = warp * 16;

    const uint32_t sQa = (uint32_t)__cvta_generic_to_shared(sQ);
    const uint32_t sKa = (uint32_t)__cvta_generic_to_shared(sK);
    const uint32_t sVa = (uint32_t)__cvta_generic_to_shared(sV);

    // ldmatrix per-lane bases (bytes)
    const uint32_t Qlm = sQa + (uint32_t)(((w16 + (lane & 15)) * QKW + (lane >> 4) * 4) * 4);
    const uint32_t Klm = sKa + (uint32_t)((((lane & 7) + (lane >> 4) * 8) * QKW + ((lane >> 3) & 1) * 4) * 4);
    const uint32_t Vlm = sVa + (uint32_t)((((lane & 7) + ((lane >> 3) & 1) * 8) * QKW + (lane >> 4) * 4) * 4);

    const __half* Qbase = Q + (size_t)b * S_ * (NH_ * HD_)  + h * HD_;
    const __half* Kbase = K + (size_t)b * S_ * (NKV_ * HD_) + kvh * HD_;
    const __half* Vbase = V + (size_t)b * S_ * (NKV_ * HD_) + kvh * HD_;

    // Q tile staging: 128 rows x 64 words
#pragma unroll
    for (int i = 0; i < 8; ++i) {
        int p = i * 256 + tid;
        int r = p >> 4, q = p & 15;
        uint4 v = *(const uint4*)(Qbase + (size_t)(q0 + r) * (NH_ * HD_) + q * 8);
        *(uint4*)&sQ[r * QKW + q * 4] = v;
    }

    float oacc[16][4];
#pragma unroll
    for (int n = 0; n < 16; ++n)
#pragma unroll
        for (int r = 0; r < 4; ++r) oacc[n][r] = 0.f;
    float m_i[2] = { -1e30f, -1e30f };
    float l_i[2] = { 0.f, 0.f };

    __syncthreads();

    const int njt = 2 * qt + 2;
    const int g  = lane >> 2;
    const int tg = lane & 3;

    for (int j = 0; j < njt; ++j) {
        const int k0 = j * 64;

        // K and V staging: 64 rows x 64 words each, uint4 copies
#pragma unroll
        for (int i = 0; i < 4; ++i) {
            int p = i * 256 + tid;
            int r = p >> 4, q = p & 15;
            uint4 kv = *(const uint4*)(Kbase + (size_t)(k0 + r) * (NKV_ * HD_) + q * 8);
            *(uint4*)&sK[r * QKW + q * 4] = kv;
            uint4 vv = *(const uint4*)(Vbase + (size_t)(k0 + r) * (NKV_ * HD_) + q * 8);
            *(uint4*)&sV[r * QKW + q * 4] = vv;
        }
        __syncthreads();

        if (k0 <= q0 + w16 + 15) {
            // ---- S = Q @ K^T ----
            float sacc[8][4];
#pragma unroll
            for (int n = 0; n < 8; ++n)
#pragma unroll
                for (int r = 0; r < 4; ++r) sacc[n][r] = 0.f;

#pragma unroll 2
            for (int ks = 0; ks < 8; ++ks) {
                uint32_t a[4];
                ldsm_x4(a[0], a[1], a[2], a[3], Qlm + ks * 32);
#pragma unroll
                for (int i = 0; i < 4; ++i) {
                    uint32_t b0, b1, b2, b3;
                    ldsm_x4(b0, b1, b2, b3, Klm + (uint32_t)(i * 16 * QKW * 4) + ks * 32);
                    uint32_t f0[2] = { b0, b1 };
                    uint32_t f1[2] = { b2, b3 };
                    mma_f16(sacc[2 * i],     a, f0);
                    mma_f16(sacc[2 * i + 1], a, f1);
                }
            }

            // ---- scale + causal mask ----
            const int r0g = q0 + w16 + g;
            const int r1g = r0g + 8;
            const bool diag = (k0 + 63 > q0 + w16);
#pragma unroll
            for (int n = 0; n < 8; ++n) {
                int cb = k0 + n * 8 + 2 * tg;
                float s0 = sacc[n][0] * SCALE_;
                float s1 = sacc[n][1] * SCALE_;
                float s2 = sacc[n][2] * SCALE_;
                float s3 = sacc[n][3] * SCALE_;
                if (diag) {
                    if (cb     > r0g) s0 = -1e30f;
                    if (cb + 1 > r0g) s1 = -1e30f;
                    if (cb     > r1g) s2 = -1e30f;
                    if (cb + 1 > r1g) s3 = -1e30f;
                }
                sacc[n][0] = s0; sacc[n][1] = s1; sacc[n][2] = s2; sacc[n][3] = s3;
            }

            // ---- online softmax ----
            float mx0 = -1e30f, mx1 = -1e30f;
#pragma unroll
            for (int n = 0; n < 8; ++n) {
                mx0 = fmaxf(mx0, fmaxf(sacc[n][0], sacc[n][1]));
                mx1 = fmaxf(mx1, fmaxf(sacc[n][2], sacc[n][3]));
            }
            mx0 = fmaxf(mx0, __shfl_xor_sync(0xffffffffu, mx0, 1));
            mx0 = fmaxf(mx0, __shfl_xor_sync(0xffffffffu, mx0, 2));
            mx1 = fmaxf(mx1, __shfl_xor_sync(0xffffffffu, mx1, 1));
            mx1 = fmaxf(mx1, __shfl_xor_sync(0xffffffffu, mx1, 2));

            float mn0 = fmaxf(m_i[0], mx0);
            float mn1 = fmaxf(m_i[1], mx1);
            float al0 = __expf(m_i[0] - mn0);
            float al1 = __expf(m_i[1] - mn1);
            m_i[0] = mn0; m_i[1] = mn1;

            uint32_t pk[8][2];
            float rs0 = 0.f, rs1 = 0.f;
#pragma unroll
            for (int n = 0; n < 8; ++n) {
                float p0 = __expf(sacc[n][0] - mn0);
                float p1 = __expf(sacc[n][1] - mn0);
                float p2 = __expf(sacc[n][2] - mn1);
                float p3 = __expf(sacc[n][3] - mn1);
                rs0 += p0 + p1;
                rs1 += p2 + p3;
                pk[n][0] = h2pack(p0, p1);
                pk[n][1] = h2pack(p2, p3);
            }
            rs0 += __shfl_xor_sync(0xffffffffu, rs0, 1);
            rs0 += __shfl_xor_sync(0xffffffffu, rs0, 2);
            rs1 += __shfl_xor_sync(0xffffffffu, rs1, 1);
            rs1 += __shfl_xor_sync(0xffffffffu, rs1, 2);
            l_i[0] = l_i[0] * al0 + rs0;
            l_i[1] = l_i[1] * al1 + rs1;

#pragma unroll
            for (int n = 0; n < 16; ++n) {
                oacc[n][0] *= al0; oacc[n][1] *= al0;
                oacc[n][2] *= al1; oacc[n][3] *= al1;
            }

            // ---- O += P @ V (V trans-loaded by ldmatrix) ----
#pragma unroll
            for (int ks = 0; ks < 4; ++ks) {
                uint32_t a[4];
                a[0] = pk[2 * ks][0];
                a[1] = pk[2 * ks][1];
                a[2] = pk[2 * ks + 1][0];
                a[3] = pk[2 * ks + 1][1];
                const uint32_t vrow = Vlm + (uint32_t)(ks * 16 * QKW * 4);
#pragma unroll 4
                for (int i = 0; i < 8; ++i) {
                    uint32_t b0, b1, b2, b3;
                    ldsm_x4_t(b0, b1, b2, b3, vrow + i * 32);
                    uint32_t f0[2] = { b0, b1 };
                    uint32_t f1[2] = { b2, b3 };
                    mma_f16(oacc[2 * i],     a, f0);
                    mma_f16(oacc[2 * i + 1], a, f1);
                }
            }
        }
        __syncthreads();
    }

    float inv0 = 1.0f / l_i[0];
    float inv1 = 1.0f / l_i[1];
    size_t t0 = (size_t)b * S_ + q0 + w16 + g;
    size_t t1 = t0 + 8;
    __half* op0 = O + t0 * (NH_ * HD_) + h * HD_;
    __half* op1 = O + t1 * (NH_ * HD_) + h * HD_;
#pragma unroll
    for (int n = 0; n < 16; ++n) {
        int c = n * 8 + 2 * tg;
        *(uint32_t*)(op0 + c) = h2pack(oacc[n][0] * inv0, oacc[n][1] * inv0);
        *(uint32_t*)(op1 + c) = h2pack(oacc[n][2] * inv1, oacc[n][3] * inv1);
    }
}

// ---------------------------------------------------------------------------
// Launch
// ---------------------------------------------------------------------------
extern "C" void kernel_launch(void* const* d_in, const int* in_sizes, int n_in,
                              void* d_out, int out_size)
{
    const float* hidden = (const float*)d_in[0];
    const int*   positions = (const int*)d_in[1];
    const float* Wq = (const float*)d_in[2];
    const float* bq = (const float*)d_in[3];
    const float* Wk = (const float*)d_in[4];
    const float* bk = (const float*)d_in[5];
    const float* Wv = (const float*)d_in[6];
    const float* bv = (const float*)d_in[7];
    const float* Wo = (const float*)d_in[8];
    float* out = (float*)d_out;

    void *pAhi, *pAlo, *pWq, *pWk, *pWv, *pWo, *pQ, *pK, *pV, *pA;
    cudaGetSymbolAddress(&pAhi, g_Ahi);
    cudaGetSymbolAddress(&pAlo, g_Alo);
    cudaGetSymbolAddress(&pWq, g_Wq_p);
    cudaGetSymbolAddress(&pWk, g_Wk_p);
    cudaGetSymbolAddress(&pWv, g_Wv_p);
    cudaGetSymbolAddress(&pWo, g_Wo_p);
    cudaGetSymbolAddress(&pQ, g_Qh);
    cudaGetSymbolAddress(&pK, g_Kh);
    cudaGetSymbolAddress(&pV, g_Vh);
    cudaGetSymbolAddress(&pA, g_ATTNh);

    uint32_t* Ahi = (uint32_t*)pAhi;
    uint32_t* Alo = (uint32_t*)pAlo;
    uint32_t* Wqp = (uint32_t*)pWq;
    uint32_t* Wkp = (uint32_t*)pWk;
    uint32_t* Wvp = (uint32_t*)pWv;
    uint32_t* Wop = (uint32_t*)pWo;
    __half* Qh = (__half*)pQ;
    __half* Kh = (__half*)pK;
    __half* Vh = (__half*)pV;
    __half* Ah = (__half*)pA;

    // Prepass packs
    {
        int nwA = T_ * (H_ / 2);
        pack_A_kernel<<<(nwA + 255) / 256, 256>>>(hidden, Ahi, Alo, nwA);
        int nq = (H_ / 2) * (NH_ * HD_);
        pack_W_kernel<<<(nq + 255) / 256, 256>>>(Wq, Wqp, H_ / 2, NH_ * HD_);
        int nk = (H_ / 2) * (NKV_ * HD_);
        pack_W_kernel<<<(nk + 255) / 256, 256>>>(Wk, Wkp, H_ / 2, NKV_ * HD_);
        pack_W_kernel<<<(nk + 255) / 256, 256>>>(Wv, Wvp, H_ / 2, NKV_ * HD_);
        int no = ((NH_ * HD_) / 2) * H_;
        pack_W_kernel<<<(no + 255) / 256, 256>>>(Wo, Wop, (NH_ * HD_) / 2, H_);
    }

    // QKV projections (2-term, half output)
    f16_gemm_packed<true><<<dim3((NH_ * HD_) / 128, T_ / 128), 256>>>(Ahi, Alo, Wqp, bq, Qh, T_, NH_ * HD_, H_);
    f16_gemm_packed<true><<<dim3((NKV_ * HD_) / 128, T_ / 128), 256>>>(Ahi, Alo, Wkp, bk, Kh, T_, NKV_ * HD_, H_);
    f16_gemm_packed<true><<<dim3((NKV_ * HD_) / 128, T_ / 128), 256>>>(Ahi, Alo, Wvp, bv, Vh, T_, NKV_ * HD_, H_);

    // RoPE on half Q/K
    {
        int totq = T_ * NH_ * 64;
        rope_h_kernel<<<(totq + 255) / 256, 256>>>(Qh, positions, T_, NH_);
        int totk = T_ * NKV_ * 64;
        rope_h_kernel<<<(totk + 255) / 256, 256>>>(Kh, positions, T_, NKV_);
    }

    // Flash attention (half in/out, ldmatrix feeds)
    size_t fa_smem = (size_t)(FA_BM2 * QKW + 64 * QKW + 64 * QKW) * sizeof(uint32_t);
    cudaFuncSetAttribute(flash_attn_fp16_kernel, cudaFuncAttributeMaxDynamicSharedMemorySize, (int)fa_smem);
    flash_attn_fp16_kernel<<<dim3(S_ / FA_BM2, NH_, B_), 256, fa_smem>>>(Qh, Kh, Vh, Ah);

    // Output projection (1-term, float out)
    f16_gemm_packed<false><<<dim3(H_ / 128, T_ / 128), 256>>>(
        (const uint32_t*)Ah, nullptr, Wop, nullptr, out, T_, H_, NH_ * HD_);
}